// round 13
// baseline (speedup 1.0000x reference)
#include <cuda_runtime.h>
#include <cuda_bf16.h>
#include <math.h>

#define BB 8
#define NN 2048
#define CC 768
#define HH 12
#define DD 64
#define F3 (3*CC)   // 2304
#define QT 128      // query rows per block
#define KT 64       // keys per tile

// Scratch (static device allocations are the sanctioned no-alloc path)
__device__ float g_qkv[(size_t)BB*NN*F3];   // [B,N,3C]  ~151 MB
__device__ float g_attn[(size_t)BB*NN*CC];  // [B,N,C]   ~50 MB

// ---------------------------------------------------------------------------
// helpers
// ---------------------------------------------------------------------------
__device__ __forceinline__ float tf32r(float x) {
    unsigned u;
    asm("cvt.rna.tf32.f32 %0, %1;" : "=r"(u) : "f"(x));
    return __uint_as_float(u);
}

// D += A(16x8 tf32) * B(8x8 tf32), fp32 accum
__device__ __forceinline__ void mma_tf32(float* c, const unsigned* a,
                                         unsigned b0, unsigned b1) {
    asm volatile(
        "mma.sync.aligned.m16n8k8.row.col.f32.tf32.tf32.f32 "
        "{%0,%1,%2,%3}, {%4,%5,%6,%7}, {%8,%9}, {%0,%1,%2,%3};"
        : "+f"(c[0]), "+f"(c[1]), "+f"(c[2]), "+f"(c[3])
        : "r"(a[0]), "r"(a[1]), "r"(a[2]), "r"(a[3]), "r"(b0), "r"(b1));
}

// ---------------------------------------------------------------------------
// tf32 tensor-core GEMM — R5 compute structure (measured best) with a
// conflict-free fill: lane-major rows (row = idx&127, c4 = idx>>7) so each
// warp's STS.128 hits banks 20*lane mod 32 -> every 8-lane phase covers all
// 32 banks once (4-phase minimum). Old mapping cost ~2-4x STS phases and L1
// was the binding pipe (80% with tensor 34%).
// C[m,n] = sum_k A[m,k]*B[n,k] (+ bias[n]); A:[M,K], B:[N,K] row-major.
// 128x128 block, BK=16, 256 thr (8 warps, warp tile 32m x 64n).
// ---------------------------------------------------------------------------
__global__ __launch_bounds__(256)
void gemm_tf32(const float* __restrict__ A, const float* __restrict__ B,
               const float* __restrict__ bias, float* __restrict__ C,
               int M, int N, int K)
{
    __shared__ __align__(16) float As[128][20];
    __shared__ __align__(16) float Bs[128][20];

    const int t    = threadIdx.x;
    const int m0   = blockIdx.y * 128;
    const int n0   = blockIdx.x * 128;
    const int wid  = t >> 5;
    const int lane = t & 31;
    const int gid  = lane >> 2;
    const int qq   = lane & 3;
    const int wm   = (wid & 3) * 32;   // warp m offset
    const int wn   = (wid >> 2) * 64;  // warp n offset

    float c[2][8][4];
    #pragma unroll
    for (int i = 0; i < 2; i++)
        #pragma unroll
        for (int j = 0; j < 8; j++)
            #pragma unroll
            for (int v = 0; v < 4; v++) c[i][j][v] = 0.f;

    for (int k0 = 0; k0 < K; k0 += 16) {
        // fill: 2 float4 of A and B per thread, conflict-free STS.128
        #pragma unroll
        for (int r = 0; r < 2; r++) {
            int idx = r * 256 + t;
            int row = idx & 127;
            int c4  = idx >> 7;        // 0..3
            const float* ap = A + (size_t)(m0 + row) * K + k0 + c4 * 4;
            float4 va = *(const float4*)ap;
            float4 ta;
            ta.x = tf32r(va.x); ta.y = tf32r(va.y);
            ta.z = tf32r(va.z); ta.w = tf32r(va.w);
            *(float4*)&As[row][c4 * 4] = ta;
            const float* bp = B + (size_t)(n0 + row) * K + k0 + c4 * 4;
            float4 vb = *(const float4*)bp;
            float4 tb;
            tb.x = tf32r(vb.x); tb.y = tf32r(vb.y);
            tb.z = tf32r(vb.z); tb.w = tf32r(vb.w);
            *(float4*)&Bs[row][c4 * 4] = tb;
        }
        __syncthreads();

        #pragma unroll
        for (int ks = 0; ks < 2; ks++) {
            unsigned a[2][4];
            #pragma unroll
            for (int mt = 0; mt < 2; mt++) {
                int mr = wm + mt * 16;
                a[mt][0] = __float_as_uint(As[mr + gid    ][ks*8 + qq    ]);
                a[mt][1] = __float_as_uint(As[mr + gid + 8][ks*8 + qq    ]);
                a[mt][2] = __float_as_uint(As[mr + gid    ][ks*8 + qq + 4]);
                a[mt][3] = __float_as_uint(As[mr + gid + 8][ks*8 + qq + 4]);
            }
            #pragma unroll
            for (int nt = 0; nt < 8; nt++) {
                unsigned bb0 = __float_as_uint(Bs[wn + nt*8 + gid][ks*8 + qq    ]);
                unsigned bb1 = __float_as_uint(Bs[wn + nt*8 + gid][ks*8 + qq + 4]);
                mma_tf32(c[0][nt], a[0], bb0, bb1);
                mma_tf32(c[1][nt], a[1], bb0, bb1);
            }
        }
        __syncthreads();
    }

    // epilogue
    #pragma unroll
    for (int nt = 0; nt < 8; nt++) {
        int col = n0 + wn + nt * 8 + 2 * qq;
        float b0 = bias ? bias[col]     : 0.f;
        float b1 = bias ? bias[col + 1] : 0.f;
        #pragma unroll
        for (int mt = 0; mt < 2; mt++) {
            int row = m0 + wm + mt * 16 + gid;
            float2 v0; v0.x = c[mt][nt][0] + b0; v0.y = c[mt][nt][1] + b1;
            float2 v1; v1.x = c[mt][nt][2] + b0; v1.y = c[mt][nt][3] + b1;
            *(float2*)(C + (size_t)row * N + col)       = v0;
            *(float2*)(C + (size_t)(row + 8) * N + col) = v1;
        }
    }
}

// ---------------------------------------------------------------------------
// Flash attention — R6 version verbatim (measured best: ~906us). All-tf32
// MMA, register-prefetch pipelined, online-max softmax. Variants falsified:
// no-max (1120us, R10), forced 2-block occupancy (1006us, R12).
// Block = (128 q-rows, head h, batch b), 256 thr (8 warps),
// warp w owns S/O strip rows [16w, 16w+16).
// ---------------------------------------------------------------------------
__global__ __launch_bounds__(256)
void attn_mma_kernel()
{
    __shared__ float pool[KT*68 + KT*72];    // Ks[64][68] + Vs[64][72]
    float (*Qs)[68] = (float(*)[68])pool;    // Qs[128][68] aliases (dead after prologue)
    float (*Ks)[68] = (float(*)[68])pool;
    float (*Vs)[72] = (float(*)[72])(pool + KT*68);

    const int b  = blockIdx.z;
    const int h  = blockIdx.y;
    const int n0 = blockIdx.x * QT;
    const int tid  = threadIdx.x;
    const int w    = tid >> 5;    // 0..7
    const int lane = tid & 31;
    const int gid  = lane >> 2;   // 0..7
    const int qq   = lane & 3;    // 0..3

    const size_t base_bn = (size_t)(b * NN) * F3;
    const float* kBase = g_qkv + base_bn + CC + h * DD;   // K rows; V at +CC

    // ---- load Q tile [128][64] (scaled, tf32-rounded) ----
    #pragma unroll
    for (int r = 0; r < 8; r++) {
        int idx = r * 256 + tid;        // 0..2047 float4s
        int row = idx >> 4;
        int c4  = idx & 15;
        const float* gp = g_qkv + base_bn + (size_t)(n0 + row) * F3 + h * DD + c4 * 4;
        float4 v = *(const float4*)gp;
        Qs[row][c4*4+0] = tf32r(v.x * 0.125f);
        Qs[row][c4*4+1] = tf32r(v.y * 0.125f);
        Qs[row][c4*4+2] = tf32r(v.z * 0.125f);
        Qs[row][c4*4+3] = tf32r(v.w * 0.125f);
    }
    __syncthreads();

    // ---- Q A-fragments (registers for whole kernel) ----
    unsigned qa[8][4];
    #pragma unroll
    for (int ks = 0; ks < 8; ks++) {
        qa[ks][0] = __float_as_uint(Qs[16*w + gid    ][8*ks + qq    ]);
        qa[ks][1] = __float_as_uint(Qs[16*w + gid + 8][8*ks + qq    ]);
        qa[ks][2] = __float_as_uint(Qs[16*w + gid    ][8*ks + qq + 4]);
        qa[ks][3] = __float_as_uint(Qs[16*w + gid + 8][8*ks + qq + 4]);
    }
    __syncthreads();   // Qs consumed; pool becomes Ks/Vs

    float o[8][4];
    #pragma unroll
    for (int t = 0; t < 8; t++)
        #pragma unroll
        for (int j = 0; j < 4; j++) o[t][j] = 0.f;
    float m0 = -1e30f, m1 = -1e30f, l0 = 0.f, l1 = 0.f;

    // ---- prefetch tile 0 (K: pf[0..3], V: pf[4..7]) ----
    float4 pf[8];
    #pragma unroll
    for (int r = 0; r < 4; r++) {
        int idx = r * 256 + tid;        // 0..1023
        int row = idx >> 4, c4 = idx & 15;
        pf[r]     = *(const float4*)(kBase + (size_t)row * F3 + c4 * 4);
        pf[r + 4] = *(const float4*)(kBase + (size_t)row * F3 + CC + c4 * 4);
    }

    for (int kt = 0; kt < NN / KT; kt++) {
        // ---- commit prefetched K/V to SMEM (tf32-rounded) ----
        #pragma unroll
        for (int r = 0; r < 4; r++) {
            int idx = r * 256 + tid;
            int row = idx >> 4, c4 = idx & 15;
            Ks[row][c4*4+0] = tf32r(pf[r].x);
            Ks[row][c4*4+1] = tf32r(pf[r].y);
            Ks[row][c4*4+2] = tf32r(pf[r].z);
            Ks[row][c4*4+3] = tf32r(pf[r].w);
            Vs[row][c4*4+0] = tf32r(pf[r+4].x);
            Vs[row][c4*4+1] = tf32r(pf[r+4].y);
            Vs[row][c4*4+2] = tf32r(pf[r+4].z);
            Vs[row][c4*4+3] = tf32r(pf[r+4].w);
        }
        __syncthreads();

        // ---- issue LDG for next tile (hidden behind compute) ----
        if (kt + 1 < NN / KT) {
            const float* kb = kBase + (size_t)((kt + 1) * KT) * F3;
            #pragma unroll
            for (int r = 0; r < 4; r++) {
                int idx = r * 256 + tid;
                int row = idx >> 4, c4 = idx & 15;
                pf[r]     = *(const float4*)(kb + (size_t)row * F3 + c4 * 4);
                pf[r + 4] = *(const float4*)(kb + (size_t)row * F3 + CC + c4 * 4);
            }
        }

        // ---- S = Q * K^T  (warp strip 16x64) ----
        float s[8][4];
        #pragma unroll
        for (int t = 0; t < 8; t++)
            #pragma unroll
            for (int j = 0; j < 4; j++) s[t][j] = 0.f;

        #pragma unroll
        for (int ks = 0; ks < 8; ks++) {
            #pragma unroll
            for (int t = 0; t < 8; t++) {
                unsigned b0 = __float_as_uint(Ks[8*t + gid][8*ks + qq    ]);
                unsigned b1 = __float_as_uint(Ks[8*t + gid][8*ks + qq + 4]);
                mma_tf32(s[t], qa[ks], b0, b1);
            }
        }

        // ---- online softmax (rows gid -> m0/l0, gid+8 -> m1/l1) ----
        float mx0 = -1e30f, mx1 = -1e30f;
        #pragma unroll
        for (int t = 0; t < 8; t++) {
            mx0 = fmaxf(mx0, fmaxf(s[t][0], s[t][1]));
            mx1 = fmaxf(mx1, fmaxf(s[t][2], s[t][3]));
        }
        mx0 = fmaxf(mx0, __shfl_xor_sync(0xffffffffu, mx0, 1));
        mx0 = fmaxf(mx0, __shfl_xor_sync(0xffffffffu, mx0, 2));
        mx1 = fmaxf(mx1, __shfl_xor_sync(0xffffffffu, mx1, 1));
        mx1 = fmaxf(mx1, __shfl_xor_sync(0xffffffffu, mx1, 2));

        float mn0 = fmaxf(m0, mx0), mn1 = fmaxf(m1, mx1);
        float cr0 = __expf(m0 - mn0), cr1 = __expf(m1 - mn1);
        l0 *= cr0; l1 *= cr1;
        m0 = mn0; m1 = mn1;
        #pragma unroll
        for (int t = 0; t < 8; t++) {
            o[t][0] *= cr0; o[t][1] *= cr0;
            o[t][2] *= cr1; o[t][3] *= cr1;
        }

        // ---- P = tf32(exp(S - m)); l sums the rounded P ----
        #pragma unroll
        for (int t = 0; t < 8; t++) {
            float p0 = tf32r(__expf(s[t][0] - m0));
            float p1 = tf32r(__expf(s[t][1] - m0));
            float p2 = tf32r(__expf(s[t][2] - m1));
            float p3 = tf32r(__expf(s[t][3] - m1));
            l0 += p0 + p1;
            l1 += p2 + p3;
            s[t][0] = p0; s[t][1] = p1; s[t][2] = p2; s[t][3] = p3;
        }

        // ---- O += P * V  (A-frags via intra-quad shuffles) ----
        #pragma unroll
        for (int ks = 0; ks < 8; ks++) {
            int srcA = (lane & ~3) | (qq >> 1);   // holder of col qq
            int srcB = srcA + 2;                  // holder of col qq+4
            float u0 = __shfl_sync(0xffffffffu, s[ks][0], srcA);
            float u1 = __shfl_sync(0xffffffffu, s[ks][1], srcA);
            float u2 = __shfl_sync(0xffffffffu, s[ks][2], srcA);
            float u3 = __shfl_sync(0xffffffffu, s[ks][3], srcA);
            float w0 = __shfl_sync(0xffffffffu, s[ks][0], srcB);
            float w1 = __shfl_sync(0xffffffffu, s[ks][1], srcB);
            float w2 = __shfl_sync(0xffffffffu, s[ks][2], srcB);
            float w3 = __shfl_sync(0xffffffffu, s[ks][3], srcB);
            bool odd = (qq & 1);
            unsigned pa[4];
            pa[0] = __float_as_uint(odd ? u1 : u0);
            pa[1] = __float_as_uint(odd ? u3 : u2);
            pa[2] = __float_as_uint(odd ? w1 : w0);
            pa[3] = __float_as_uint(odd ? w3 : w2);

            #pragma unroll
            for (int ot = 0; ot < 8; ot++) {
                unsigned vb0 = __float_as_uint(Vs[8*ks + qq    ][8*ot + gid]);
                unsigned vb1 = __float_as_uint(Vs[8*ks + qq + 4][8*ot + gid]);
                mma_tf32(o[ot], pa, vb0, vb1);
            }
        }
        __syncthreads();   // tile consumed before next commit
    }

    // ---- finalize: reduce l across quad, normalize, store ----
    l0 += __shfl_xor_sync(0xffffffffu, l0, 1);
    l0 += __shfl_xor_sync(0xffffffffu, l0, 2);
    l1 += __shfl_xor_sync(0xffffffffu, l1, 1);
    l1 += __shfl_xor_sync(0xffffffffu, l1, 2);
    const float inv0 = 1.f / l0, inv1 = 1.f / l1;

    float* op0 = g_attn + (size_t)(b * NN + n0 + 16*w + gid) * CC + h * DD;
    float* op1 = op0 + (size_t)8 * CC;
    #pragma unroll
    for (int ot = 0; ot < 8; ot++) {
        float2 v0; v0.x = o[ot][0] * inv0; v0.y = o[ot][1] * inv0;
        float2 v1; v1.x = o[ot][2] * inv1; v1.y = o[ot][3] * inv1;
        *(float2*)(op0 + 8*ot + 2*qq) = v0;
        *(float2*)(op1 + 8*ot + 2*qq) = v1;
    }
}

// ---------------------------------------------------------------------------
extern "C" void kernel_launch(void* const* d_in, const int* in_sizes, int n_in,
                              void* d_out, int out_size)
{
    const float* x      = (const float*)d_in[0];
    const float* w_qkv  = (const float*)d_in[1];
    const float* w_proj = (const float*)d_in[2];
    const float* b_proj = (const float*)d_in[3];
    float* out = (float*)d_out;

    float *qkv_ptr, *attn_ptr;
    cudaGetSymbolAddress((void**)&qkv_ptr,  g_qkv);
    cudaGetSymbolAddress((void**)&attn_ptr, g_attn);

    const int M = BB * NN;   // 16384

    // 1) QKV GEMM: [16384,768] x [2304,768]^T -> [16384,2304]
    {
        dim3 grid(F3 / 128, M / 128);
        gemm_tf32<<<grid, 256>>>(x, w_qkv, nullptr, qkv_ptr, M, F3, CC);
    }

    // 2) Attention (tensor cores)
    {
        dim3 grid(NN / QT, HH, BB);
        attn_mma_kernel<<<grid, 256>>>();
    }

    // 3) Proj GEMM + bias: [16384,768] x [768,768]^T -> [16384,768]
    {
        dim3 grid(CC / 128, M / 128);
        gemm_tf32<<<grid, 256>>>(attn_ptr, w_proj, b_proj, out, M, CC, CC);
    }
}

// round 14
// speedup vs baseline: 1.2189x; 1.2189x over previous
#include <cuda_runtime.h>
#include <cuda_bf16.h>
#include <math.h>

#define BB 8
#define NN 2048
#define CC 768
#define HH 12
#define DD 64
#define F3 (3*CC)   // 2304
#define QT 128      // query rows per block
#define KT 64       // keys per tile

// Scratch (static device allocations are the sanctioned no-alloc path)
__device__ float g_qkv[(size_t)BB*NN*F3];   // [B,N,3C]  ~151 MB
__device__ float g_attn[(size_t)BB*NN*CC];  // [B,N,C]   ~50 MB

// ---------------------------------------------------------------------------
// helpers
// ---------------------------------------------------------------------------
__device__ __forceinline__ float tf32r(float x) {
    unsigned u;
    asm("cvt.rna.tf32.f32 %0, %1;" : "=r"(u) : "f"(x));
    return __uint_as_float(u);
}

// D += A(16x8 tf32) * B(8x8 tf32), fp32 accum
__device__ __forceinline__ void mma_tf32(float* c, const unsigned* a,
                                         unsigned b0, unsigned b1) {
    asm volatile(
        "mma.sync.aligned.m16n8k8.row.col.f32.tf32.tf32.f32 "
        "{%0,%1,%2,%3}, {%4,%5,%6,%7}, {%8,%9}, {%0,%1,%2,%3};"
        : "+f"(c[0]), "+f"(c[1]), "+f"(c[2]), "+f"(c[3])
        : "r"(a[0]), "r"(a[1]), "r"(a[2]), "r"(a[3]), "r"(b0), "r"(b1));
}

// ---------------------------------------------------------------------------
// tf32 tensor-core GEMM — R5 structure with BK=32 (halved sync count).
// C[m,n] = sum_k A[m,k]*B[n,k] (+ bias[n]); A:[M,K], B:[N,K] row-major.
// 128x128 block, 256 thr (8 warps, warp tile 32m x 64n), regs ~100
// -> 2 blocks/SM. Fill keeps R5's load shape (2 lanes/row, contiguous
// chunks); 24 sync pairs for K=768 instead of 48 -> each post-barrier
// pipeline refill amortizes over 2x the mma work (kernel is issue/latency
// bound: R13 falsified crossbar, R6-R8 falsified reg-prefetch/big-tiles).
// SMEM [row][k] stride 36 -> fragment reads conflict-free (4*gid banks).
// K must be a multiple of 32 (768 ok).
// ---------------------------------------------------------------------------
__global__ __launch_bounds__(256)
void gemm_tf32(const float* __restrict__ A, const float* __restrict__ B,
               const float* __restrict__ bias, float* __restrict__ C,
               int M, int N, int K)
{
    __shared__ float As[128][36];
    __shared__ float Bs[128][36];

    const int t    = threadIdx.x;
    const int m0   = blockIdx.y * 128;
    const int n0   = blockIdx.x * 128;
    const int wid  = t >> 5;
    const int lane = t & 31;
    const int gid  = lane >> 2;
    const int qq   = lane & 3;
    const int wm   = (wid & 3) * 32;   // warp m offset
    const int wn   = (wid >> 2) * 64;  // warp n offset

    const int lrow = t >> 1;           // 0..127 (fill row)
    const int lc16 = (t & 1) * 16;     // 0 or 16 (fill k-offset)

    const float* aRow = A + (size_t)(m0 + lrow) * K + lc16;
    const float* bRow = B + (size_t)(n0 + lrow) * K + lc16;

    float c[2][8][4];
    #pragma unroll
    for (int i = 0; i < 2; i++)
        #pragma unroll
        for (int j = 0; j < 8; j++)
            #pragma unroll
            for (int v = 0; v < 4; v++) c[i][j][v] = 0.f;

    for (int k0 = 0; k0 < K; k0 += 32) {
        // fill: thread loads 16 floats of A and 16 of B (4 LDG.128 each)
        #pragma unroll
        for (int q = 0; q < 4; q++) {
            float4 va = *(const float4*)(aRow + k0 + q * 4);
            As[lrow][lc16+q*4+0] = tf32r(va.x);
            As[lrow][lc16+q*4+1] = tf32r(va.y);
            As[lrow][lc16+q*4+2] = tf32r(va.z);
            As[lrow][lc16+q*4+3] = tf32r(va.w);
            float4 vb = *(const float4*)(bRow + k0 + q * 4);
            Bs[lrow][lc16+q*4+0] = tf32r(vb.x);
            Bs[lrow][lc16+q*4+1] = tf32r(vb.y);
            Bs[lrow][lc16+q*4+2] = tf32r(vb.z);
            Bs[lrow][lc16+q*4+3] = tf32r(vb.w);
        }
        __syncthreads();

        #pragma unroll
        for (int ks = 0; ks < 4; ks++) {
            unsigned a[2][4];
            #pragma unroll
            for (int mt = 0; mt < 2; mt++) {
                int mr = wm + mt * 16;
                a[mt][0] = __float_as_uint(As[mr + gid    ][ks*8 + qq    ]);
                a[mt][1] = __float_as_uint(As[mr + gid + 8][ks*8 + qq    ]);
                a[mt][2] = __float_as_uint(As[mr + gid    ][ks*8 + qq + 4]);
                a[mt][3] = __float_as_uint(As[mr + gid + 8][ks*8 + qq + 4]);
            }
            #pragma unroll
            for (int nt = 0; nt < 8; nt++) {
                unsigned bb0 = __float_as_uint(Bs[wn + nt*8 + gid][ks*8 + qq    ]);
                unsigned bb1 = __float_as_uint(Bs[wn + nt*8 + gid][ks*8 + qq + 4]);
                mma_tf32(c[0][nt], a[0], bb0, bb1);
                mma_tf32(c[1][nt], a[1], bb0, bb1);
            }
        }
        __syncthreads();
    }

    // epilogue
    #pragma unroll
    for (int nt = 0; nt < 8; nt++) {
        int col = n0 + wn + nt * 8 + 2 * qq;
        float b0 = bias ? bias[col]     : 0.f;
        float b1 = bias ? bias[col + 1] : 0.f;
        #pragma unroll
        for (int mt = 0; mt < 2; mt++) {
            int row = m0 + wm + mt * 16 + gid;
            float2 v0; v0.x = c[mt][nt][0] + b0; v0.y = c[mt][nt][1] + b1;
            float2 v1; v1.x = c[mt][nt][2] + b0; v1.y = c[mt][nt][3] + b1;
            *(float2*)(C + (size_t)row * N + col)       = v0;
            *(float2*)(C + (size_t)(row + 8) * N + col) = v1;
        }
    }
}

// ---------------------------------------------------------------------------
// Flash attention — R6 version verbatim (measured best: ~906us). All-tf32
// MMA, register-prefetch pipelined, online-max softmax. Variants falsified:
// no-max (1120us, R10), forced 2-block occupancy (1006us, R12).
// Block = (128 q-rows, head h, batch b), 256 thr (8 warps),
// warp w owns S/O strip rows [16w, 16w+16).
// ---------------------------------------------------------------------------
__global__ __launch_bounds__(256)
void attn_mma_kernel()
{
    __shared__ float pool[KT*68 + KT*72];    // Ks[64][68] + Vs[64][72]
    float (*Qs)[68] = (float(*)[68])pool;    // Qs[128][68] aliases (dead after prologue)
    float (*Ks)[68] = (float(*)[68])pool;
    float (*Vs)[72] = (float(*)[72])(pool + KT*68);

    const int b  = blockIdx.z;
    const int h  = blockIdx.y;
    const int n0 = blockIdx.x * QT;
    const int tid  = threadIdx.x;
    const int w    = tid >> 5;    // 0..7
    const int lane = tid & 31;
    const int gid  = lane >> 2;   // 0..7
    const int qq   = lane & 3;    // 0..3

    const size_t base_bn = (size_t)(b * NN) * F3;
    const float* kBase = g_qkv + base_bn + CC + h * DD;   // K rows; V at +CC

    // ---- load Q tile [128][64] (scaled, tf32-rounded) ----
    #pragma unroll
    for (int r = 0; r < 8; r++) {
        int idx = r * 256 + tid;        // 0..2047 float4s
        int row = idx >> 4;
        int c4  = idx & 15;
        const float* gp = g_qkv + base_bn + (size_t)(n0 + row) * F3 + h * DD + c4 * 4;
        float4 v = *(const float4*)gp;
        Qs[row][c4*4+0] = tf32r(v.x * 0.125f);
        Qs[row][c4*4+1] = tf32r(v.y * 0.125f);
        Qs[row][c4*4+2] = tf32r(v.z * 0.125f);
        Qs[row][c4*4+3] = tf32r(v.w * 0.125f);
    }
    __syncthreads();

    // ---- Q A-fragments (registers for whole kernel) ----
    unsigned qa[8][4];
    #pragma unroll
    for (int ks = 0; ks < 8; ks++) {
        qa[ks][0] = __float_as_uint(Qs[16*w + gid    ][8*ks + qq    ]);
        qa[ks][1] = __float_as_uint(Qs[16*w + gid + 8][8*ks + qq    ]);
        qa[ks][2] = __float_as_uint(Qs[16*w + gid    ][8*ks + qq + 4]);
        qa[ks][3] = __float_as_uint(Qs[16*w + gid + 8][8*ks + qq + 4]);
    }
    __syncthreads();   // Qs consumed; pool becomes Ks/Vs

    float o[8][4];
    #pragma unroll
    for (int t = 0; t < 8; t++)
        #pragma unroll
        for (int j = 0; j < 4; j++) o[t][j] = 0.f;
    float m0 = -1e30f, m1 = -1e30f, l0 = 0.f, l1 = 0.f;

    // ---- prefetch tile 0 (K: pf[0..3], V: pf[4..7]) ----
    float4 pf[8];
    #pragma unroll
    for (int r = 0; r < 4; r++) {
        int idx = r * 256 + tid;        // 0..1023
        int row = idx >> 4, c4 = idx & 15;
        pf[r]     = *(const float4*)(kBase + (size_t)row * F3 + c4 * 4);
        pf[r + 4] = *(const float4*)(kBase + (size_t)row * F3 + CC + c4 * 4);
    }

    for (int kt = 0; kt < NN / KT; kt++) {
        // ---- commit prefetched K/V to SMEM (tf32-rounded) ----
        #pragma unroll
        for (int r = 0; r < 4; r++) {
            int idx = r * 256 + tid;
            int row = idx >> 4, c4 = idx & 15;
            Ks[row][c4*4+0] = tf32r(pf[r].x);
            Ks[row][c4*4+1] = tf32r(pf[r].y);
            Ks[row][c4*4+2] = tf32r(pf[r].z);
            Ks[row][c4*4+3] = tf32r(pf[r].w);
            Vs[row][c4*4+0] = tf32r(pf[r+4].x);
            Vs[row][c4*4+1] = tf32r(pf[r+4].y);
            Vs[row][c4*4+2] = tf32r(pf[r+4].z);
            Vs[row][c4*4+3] = tf32r(pf[r+4].w);
        }
        __syncthreads();

        // ---- issue LDG for next tile (hidden behind compute) ----
        if (kt + 1 < NN / KT) {
            const float* kb = kBase + (size_t)((kt + 1) * KT) * F3;
            #pragma unroll
            for (int r = 0; r < 4; r++) {
                int idx = r * 256 + tid;
                int row = idx >> 4, c4 = idx & 15;
                pf[r]     = *(const float4*)(kb + (size_t)row * F3 + c4 * 4);
                pf[r + 4] = *(const float4*)(kb + (size_t)row * F3 + CC + c4 * 4);
            }
        }

        // ---- S = Q * K^T  (warp strip 16x64) ----
        float s[8][4];
        #pragma unroll
        for (int t = 0; t < 8; t++)
            #pragma unroll
            for (int j = 0; j < 4; j++) s[t][j] = 0.f;

        #pragma unroll
        for (int ks = 0; ks < 8; ks++) {
            #pragma unroll
            for (int t = 0; t < 8; t++) {
                unsigned b0 = __float_as_uint(Ks[8*t + gid][8*ks + qq    ]);
                unsigned b1 = __float_as_uint(Ks[8*t + gid][8*ks + qq + 4]);
                mma_tf32(s[t], qa[ks], b0, b1);
            }
        }

        // ---- online softmax (rows gid -> m0/l0, gid+8 -> m1/l1) ----
        float mx0 = -1e30f, mx1 = -1e30f;
        #pragma unroll
        for (int t = 0; t < 8; t++) {
            mx0 = fmaxf(mx0, fmaxf(s[t][0], s[t][1]));
            mx1 = fmaxf(mx1, fmaxf(s[t][2], s[t][3]));
        }
        mx0 = fmaxf(mx0, __shfl_xor_sync(0xffffffffu, mx0, 1));
        mx0 = fmaxf(mx0, __shfl_xor_sync(0xffffffffu, mx0, 2));
        mx1 = fmaxf(mx1, __shfl_xor_sync(0xffffffffu, mx1, 1));
        mx1 = fmaxf(mx1, __shfl_xor_sync(0xffffffffu, mx1, 2));

        float mn0 = fmaxf(m0, mx0), mn1 = fmaxf(m1, mx1);
        float cr0 = __expf(m0 - mn0), cr1 = __expf(m1 - mn1);
        l0 *= cr0; l1 *= cr1;
        m0 = mn0; m1 = mn1;
        #pragma unroll
        for (int t = 0; t < 8; t++) {
            o[t][0] *= cr0; o[t][1] *= cr0;
            o[t][2] *= cr1; o[t][3] *= cr1;
        }

        // ---- P = tf32(exp(S - m)); l sums the rounded P ----
        #pragma unroll
        for (int t = 0; t < 8; t++) {
            float p0 = tf32r(__expf(s[t][0] - m0));
            float p1 = tf32r(__expf(s[t][1] - m0));
            float p2 = tf32r(__expf(s[t][2] - m1));
            float p3 = tf32r(__expf(s[t][3] - m1));
            l0 += p0 + p1;
            l1 += p2 + p3;
            s[t][0] = p0; s[t][1] = p1; s[t][2] = p2; s[t][3] = p3;
        }

        // ---- O += P * V  (A-frags via intra-quad shuffles) ----
        #pragma unroll
        for (int ks = 0; ks < 8; ks++) {
            int srcA = (lane & ~3) | (qq >> 1);   // holder of col qq
            int srcB = srcA + 2;                  // holder of col qq+4
            float u0 = __shfl_sync(0xffffffffu, s[ks][0], srcA);
            float u1 = __shfl_sync(0xffffffffu, s[ks][1], srcA);
            float u2 = __shfl_sync(0xffffffffu, s[ks][2], srcA);
            float u3 = __shfl_sync(0xffffffffu, s[ks][3], srcA);
            float w0 = __shfl_sync(0xffffffffu, s[ks][0], srcB);
            float w1 = __shfl_sync(0xffffffffu, s[ks][1], srcB);
            float w2 = __shfl_sync(0xffffffffu, s[ks][2], srcB);
            float w3 = __shfl_sync(0xffffffffu, s[ks][3], srcB);
            bool odd = (qq & 1);
            unsigned pa[4];
            pa[0] = __float_as_uint(odd ? u1 : u0);
            pa[1] = __float_as_uint(odd ? u3 : u2);
            pa[2] = __float_as_uint(odd ? w1 : w0);
            pa[3] = __float_as_uint(odd ? w3 : w2);

            #pragma unroll
            for (int ot = 0; ot < 8; ot++) {
                unsigned vb0 = __float_as_uint(Vs[8*ks + qq    ][8*ot + gid]);
                unsigned vb1 = __float_as_uint(Vs[8*ks + qq + 4][8*ot + gid]);
                mma_tf32(o[ot], pa, vb0, vb1);
            }
        }
        __syncthreads();   // tile consumed before next commit
    }

    // ---- finalize: reduce l across quad, normalize, store ----
    l0 += __shfl_xor_sync(0xffffffffu, l0, 1);
    l0 += __shfl_xor_sync(0xffffffffu, l0, 2);
    l1 += __shfl_xor_sync(0xffffffffu, l1, 1);
    l1 += __shfl_xor_sync(0xffffffffu, l1, 2);
    const float inv0 = 1.f / l0, inv1 = 1.f / l1;

    float* op0 = g_attn + (size_t)(b * NN + n0 + 16*w + gid) * CC + h * DD;
    float* op1 = op0 + (size_t)8 * CC;
    #pragma unroll
    for (int ot = 0; ot < 8; ot++) {
        float2 v0; v0.x = o[ot][0] * inv0; v0.y = o[ot][1] * inv0;
        float2 v1; v1.x = o[ot][2] * inv1; v1.y = o[ot][3] * inv1;
        *(float2*)(op0 + 8*ot + 2*qq) = v0;
        *(float2*)(op1 + 8*ot + 2*qq) = v1;
    }
}

// ---------------------------------------------------------------------------
extern "C" void kernel_launch(void* const* d_in, const int* in_sizes, int n_in,
                              void* d_out, int out_size)
{
    const float* x      = (const float*)d_in[0];
    const float* w_qkv  = (const float*)d_in[1];
    const float* w_proj = (const float*)d_in[2];
    const float* b_proj = (const float*)d_in[3];
    float* out = (float*)d_out;

    float *qkv_ptr, *attn_ptr;
    cudaGetSymbolAddress((void**)&qkv_ptr,  g_qkv);
    cudaGetSymbolAddress((void**)&attn_ptr, g_attn);

    const int M = BB * NN;   // 16384

    // 1) QKV GEMM: [16384,768] x [2304,768]^T -> [16384,2304]
    {
        dim3 grid(F3 / 128, M / 128);
        gemm_tf32<<<grid, 256>>>(x, w_qkv, nullptr, qkv_ptr, M, F3, CC);
    }

    // 2) Attention (tensor cores)
    {
        dim3 grid(NN / QT, HH, BB);
        attn_mma_kernel<<<grid, 256>>>();
    }

    // 3) Proj GEMM + bias: [16384,768] x [768,768]^T -> [16384,768]
    {
        dim3 grid(CC / 128, M / 128);
        gemm_tf32<<<grid, 256>>>(attn_ptr, w_proj, b_proj, out, M, CC, CC);
    }
}